// round 1
// baseline (speedup 1.0000x reference)
#include <cuda_runtime.h>
#include <cstdint>

// Problem constants
#define Bn  8
#define Cc  512
#define Ln  4096
#define Hh  8
#define Dh  64
#define NSPLIT 4

// Scratch: q, k, v, att, z, y (each B*C*L = 16777216 floats), h (2x), ctx partials
// total = 8*16777216 + 1048576 = 135266304 floats (~541 MB, zero-init bss)
__device__ float g_scratch[135266304];

// ---------------------------------------------------------------------------
// Generic channel-first NN GEMM: Out[b,m,n] = sum_k W[m,k] * X[b,k,n] + bias[m]
// optional residual add (Res same layout as Out) and ELU activation.
// Tiles: 128x128x8, 256 threads, 8x8 per thread. N fixed = Ln = 4096.
// ---------------------------------------------------------------------------
__global__ __launch_bounds__(256) void gemm_nn(
    const float* __restrict__ W, const float* __restrict__ bias,
    const float* __restrict__ X, float* __restrict__ Out,
    const float* __restrict__ Res, int M, int K, int act)
{
    const int N = Ln;
    int b = blockIdx.z;
    const float* Xb = X + (size_t)b * K * N;
    float* Ob = Out + (size_t)b * M * N;
    const float* Rb = Res ? (Res + (size_t)b * M * N) : nullptr;

    __shared__ float As[8][128];
    __shared__ float Bs[8][128];

    int m0 = blockIdx.y * 128;
    int n0 = blockIdx.x * 128;
    int tid = threadIdx.x;
    int tx = tid & 15;      // 0..15
    int ty = tid >> 4;      // 0..15

    // A tile loader: 128 rows x 8 cols; 2 threads per row, float4 each
    int arow = tid >> 1;            // 0..127
    int acol = (tid & 1) * 4;       // 0 or 4
    // B tile loader: 8 rows x 128 cols; float4 each
    int bkr = tid >> 5;             // 0..7
    int bnc = (tid & 31) * 4;       // 0..124

    const float* Aptr = W + (size_t)(m0 + arow) * K + acol;
    const float* Bptr = Xb + (size_t)bkr * N + n0 + bnc;

    float acc[8][8];
    #pragma unroll
    for (int i = 0; i < 8; i++)
        #pragma unroll
        for (int j = 0; j < 8; j++) acc[i][j] = 0.f;

    for (int k0 = 0; k0 < K; k0 += 8) {
        float4 a4 = *(const float4*)(Aptr + k0);
        float4 b4 = *(const float4*)(Bptr + (size_t)k0 * N);
        __syncthreads();
        As[acol + 0][arow] = a4.x;
        As[acol + 1][arow] = a4.y;
        As[acol + 2][arow] = a4.z;
        As[acol + 3][arow] = a4.w;
        *(float4*)&Bs[bkr][bnc] = b4;
        __syncthreads();
        #pragma unroll
        for (int kk = 0; kk < 8; kk++) {
            float4 a0 = *(const float4*)&As[kk][ty * 8];
            float4 a1 = *(const float4*)&As[kk][ty * 8 + 4];
            float4 c0 = *(const float4*)&Bs[kk][tx * 8];
            float4 c1 = *(const float4*)&Bs[kk][tx * 8 + 4];
            float av[8] = {a0.x, a0.y, a0.z, a0.w, a1.x, a1.y, a1.z, a1.w};
            float bv[8] = {c0.x, c0.y, c0.z, c0.w, c1.x, c1.y, c1.z, c1.w};
            #pragma unroll
            for (int i = 0; i < 8; i++)
                #pragma unroll
                for (int j = 0; j < 8; j++)
                    acc[i][j] += av[i] * bv[j];
        }
    }

    // Epilogue: bias, optional residual, optional ELU, vectorized store
    #pragma unroll
    for (int i = 0; i < 8; i++) {
        int m = m0 + ty * 8 + i;
        float bi = bias[m];
        size_t off = (size_t)m * N + n0 + tx * 8;
        float vals[8];
        #pragma unroll
        for (int j = 0; j < 8; j++) {
            float vv = acc[i][j] + bi;
            if (Rb) vv += Rb[off + j];
            if (act) vv = vv > 0.f ? vv : expm1f(vv);
            vals[j] = vv;
        }
        *(float4*)&Ob[off]     = make_float4(vals[0], vals[1], vals[2], vals[3]);
        *(float4*)&Ob[off + 4] = make_float4(vals[4], vals[5], vals[6], vals[7]);
    }
}

// ---------------------------------------------------------------------------
// Softmax over the length dim (contiguous rows of Ln). One block per row.
// ---------------------------------------------------------------------------
__global__ __launch_bounds__(256) void softmax_len(float* __restrict__ data)
{
    __shared__ float red[256];
    float* p = data + (size_t)blockIdx.x * Ln;
    int t = threadIdx.x;
    float v[16];
    float m = -1e30f;
    #pragma unroll
    for (int i = 0; i < 16; i++) { v[i] = p[t + 256 * i]; m = fmaxf(m, v[i]); }
    red[t] = m; __syncthreads();
    for (int off = 128; off > 0; off >>= 1) {
        if (t < off) red[t] = fmaxf(red[t], red[t + off]);
        __syncthreads();
    }
    m = red[0];
    __syncthreads();
    float s = 0.f;
    #pragma unroll
    for (int i = 0; i < 16; i++) { v[i] = __expf(v[i] - m); s += v[i]; }
    red[t] = s; __syncthreads();
    for (int off = 128; off > 0; off >>= 1) {
        if (t < off) red[t] += red[t + off];
        __syncthreads();
    }
    float inv = 1.f / red[0];
    #pragma unroll
    for (int i = 0; i < 16; i++) p[t + 256 * i] = v[i] * inv;
}

// ---------------------------------------------------------------------------
// Softmax over the head-channel dim (Dh=64, stride Ln). One thread per (bh,l).
// ---------------------------------------------------------------------------
__global__ __launch_bounds__(256) void softmax_head(float* __restrict__ q)
{
    int l = blockIdx.x * 256 + threadIdx.x;
    int bh = blockIdx.y;   // b*Hh + h
    float* base = q + (size_t)bh * Dh * Ln + l;
    float v[64];
    float m = -1e30f;
    #pragma unroll
    for (int d = 0; d < 64; d++) { v[d] = base[(size_t)d * Ln]; m = fmaxf(m, v[d]); }
    float s = 0.f;
    #pragma unroll
    for (int d = 0; d < 64; d++) { v[d] = __expf(v[d] - m); s += v[d]; }
    float inv = 1.f / s;
    #pragma unroll
    for (int d = 0; d < 64; d++) base[(size_t)d * Ln] = v[d] * inv;
}

// ---------------------------------------------------------------------------
// ctx[s][bh][dk][dv] partials = sum over l-slice of kh[dk,l]*vh[dv,l]
// grid (64, NSPLIT), block 256 (16x16 threads, 4x4 outputs each)
// ---------------------------------------------------------------------------
__global__ __launch_bounds__(256) void ctx_kernel(
    const float* __restrict__ kk, const float* __restrict__ vv,
    float* __restrict__ ctxp)
{
    int bh = blockIdx.x;
    int sp = blockIdx.y;
    const float* kb = kk + (size_t)bh * Dh * Ln;
    const float* vb = vv + (size_t)bh * Dh * Ln;

    __shared__ float ks[64][33];
    __shared__ float vs[64][33];

    int tid = threadIdx.x;
    int lt = tid & 31, dr = tid >> 5;   // loader mapping
    int tx = tid & 15, ty = tid >> 4;   // compute mapping

    float acc[4][4];
    #pragma unroll
    for (int i = 0; i < 4; i++)
        #pragma unroll
        for (int j = 0; j < 4; j++) acc[i][j] = 0.f;

    int lbeg = sp * (Ln / NSPLIT);
    int lend = lbeg + (Ln / NSPLIT);
    for (int l0 = lbeg; l0 < lend; l0 += 32) {
        __syncthreads();
        #pragma unroll
        for (int r = 0; r < 8; r++) {
            int dk = dr + 8 * r;
            ks[dk][lt] = kb[(size_t)dk * Ln + l0 + lt];
            vs[dk][lt] = vb[(size_t)dk * Ln + l0 + lt];
        }
        __syncthreads();
        #pragma unroll
        for (int l2 = 0; l2 < 32; l2++) {
            float av[4], bw[4];
            #pragma unroll
            for (int i = 0; i < 4; i++) av[i] = ks[ty * 4 + i][l2];
            #pragma unroll
            for (int j = 0; j < 4; j++) bw[j] = vs[tx * 4 + j][l2];
            #pragma unroll
            for (int i = 0; i < 4; i++)
                #pragma unroll
                for (int j = 0; j < 4; j++)
                    acc[i][j] += av[i] * bw[j];
        }
    }
    #pragma unroll
    for (int i = 0; i < 4; i++)
        #pragma unroll
        for (int j = 0; j < 4; j++) {
            int dk = ty * 4 + i, dv = tx * 4 + j;
            ctxp[(((size_t)sp * 64 + bh) * 64 + dk) * 64 + dv] = acc[i][j];
        }
}

// ---------------------------------------------------------------------------
// att[bh, dv, l] = sum_dk ctx[bh,dk,dv] * qh[bh,dk,l]
// grid (Ln/256, 64); ctx partials reduced while loading into smem.
// ---------------------------------------------------------------------------
__global__ __launch_bounds__(256) void att_kernel(
    const float* __restrict__ ctxp, const float* __restrict__ q,
    float* __restrict__ att)
{
    int bh = blockIdx.y;
    __shared__ float cs[64][64];
    int tid = threadIdx.x;

    // Reduce NSPLIT partials into smem (4096 floats = 1024 float4)
    float4* cs4 = (float4*)cs;
    #pragma unroll
    for (int r = 0; r < 4; r++) {
        int idx = tid + 256 * r;
        float4 sum = make_float4(0.f, 0.f, 0.f, 0.f);
        #pragma unroll
        for (int s = 0; s < NSPLIT; s++) {
            const float4* p = (const float4*)(ctxp + ((size_t)s * 64 + bh) * 4096);
            float4 t = p[idx];
            sum.x += t.x; sum.y += t.y; sum.z += t.z; sum.w += t.w;
        }
        cs4[idx] = sum;
    }
    __syncthreads();

    int l = blockIdx.x * 256 + tid;
    const float* qb = q + (size_t)bh * Dh * Ln + l;
    float acc[64];
    #pragma unroll
    for (int d = 0; d < 64; d++) acc[d] = 0.f;

    #pragma unroll 4
    for (int dk = 0; dk < 64; dk++) {
        float qv = qb[(size_t)dk * Ln];
        #pragma unroll
        for (int j = 0; j < 16; j++) {
            float4 c4 = *(const float4*)&cs[dk][j * 4];
            acc[4 * j + 0] += c4.x * qv;
            acc[4 * j + 1] += c4.y * qv;
            acc[4 * j + 2] += c4.z * qv;
            acc[4 * j + 3] += c4.w * qv;
        }
    }
    float* ab = att + (size_t)bh * Dh * Ln + l;
    #pragma unroll
    for (int dv = 0; dv < 64; dv++) ab[(size_t)dv * Ln] = acc[dv];
}

// ---------------------------------------------------------------------------
// Channel LayerNorm over C=512 (stride Ln), channel-first in AND out.
// grid = Bn * (Ln/32); block 256 = 8 c-groups x 32 l. Two passes over input.
// ---------------------------------------------------------------------------
__global__ __launch_bounds__(256) void ln_kernel(
    const float* __restrict__ in, float* __restrict__ out,
    const float* __restrict__ g, const float* __restrict__ be)
{
    __shared__ float ss[8][32], sq[8][32], smean[32], srstd[32];
    int blk = blockIdx.x;
    int b = blk >> 7;                       // /128
    int li = threadIdx.x & 31;
    int l = ((blk & 127) << 5) + li;
    int r = threadIdx.x >> 5;               // 0..7
    const float* base = in + (size_t)b * Cc * Ln + l;

    float s = 0.f, s2 = 0.f;
    #pragma unroll
    for (int k2 = 0; k2 < 64; k2++) {
        int c = r * 64 + k2;
        float x = base[(size_t)c * Ln];
        s += x; s2 += x * x;
    }
    ss[r][li] = s; sq[r][li] = s2;
    __syncthreads();
    if (r == 0) {
        float ts = ss[0][li], t2 = sq[0][li];
        #pragma unroll
        for (int rr = 1; rr < 8; rr++) { ts += ss[rr][li]; t2 += sq[rr][li]; }
        float mean = ts * (1.f / 512.f);
        float var = t2 * (1.f / 512.f) - mean * mean;
        smean[li] = mean;
        srstd[li] = rsqrtf(var + 1e-5f);
    }
    __syncthreads();
    float mean = smean[li], rstd = srstd[li];
    float* ob = out + (size_t)b * Cc * Ln + l;
    #pragma unroll
    for (int k2 = 0; k2 < 64; k2++) {
        int c = r * 64 + k2;
        float x = base[(size_t)c * Ln];
        ob[(size_t)c * Ln] = (x - mean) * rstd * g[c] + be[c];
    }
}

// ---------------------------------------------------------------------------
extern "C" void kernel_launch(void* const* d_in, const int* in_sizes, int n_in,
                              void* d_out, int out_size)
{
    const float* z1  = (const float*)d_in[0];
    const float* z2  = (const float*)d_in[1];
    const float* Wq  = (const float*)d_in[2];
    const float* bq  = (const float*)d_in[3];
    const float* Wk  = (const float*)d_in[4];
    const float* bkb = (const float*)d_in[5];
    const float* Wv  = (const float*)d_in[6];
    const float* bv  = (const float*)d_in[7];
    const float* Wr  = (const float*)d_in[8];
    const float* br  = (const float*)d_in[9];
    const float* g1  = (const float*)d_in[10];
    const float* be1 = (const float*)d_in[11];
    const float* W1  = (const float*)d_in[12];
    const float* b1  = (const float*)d_in[13];
    const float* W2  = (const float*)d_in[14];
    const float* b2  = (const float*)d_in[15];
    const float* g2  = (const float*)d_in[16];
    const float* be2 = (const float*)d_in[17];

    float* base = nullptr;
    cudaGetSymbolAddress((void**)&base, g_scratch);
    const size_t SZ = (size_t)Bn * Cc * Ln;   // 16777216
    float* q    = base;
    float* k    = base + SZ;
    float* v    = base + 2 * SZ;
    float* att  = base + 3 * SZ;
    float* z    = base + 4 * SZ;
    float* y    = base + 5 * SZ;
    float* h    = base + 6 * SZ;              // 2*SZ floats
    float* ctxp = base + 8 * SZ;              // NSPLIT*64*64*64 floats

    dim3 thr(256);
    // Projections
    gemm_nn<<<dim3(32, 4, 8), thr>>>(Wq, bq, z1, q, nullptr, 512, 512, 0);
    gemm_nn<<<dim3(32, 4, 8), thr>>>(Wk, bkb, z2, k, nullptr, 512, 512, 0);
    gemm_nn<<<dim3(32, 4, 8), thr>>>(Wv, bv, z2, v, nullptr, 512, 512, 0);
    // Softmaxes
    softmax_len<<<Bn * Cc, thr>>>(k);
    softmax_head<<<dim3(Ln / 256, Bn * Hh), thr>>>(q);
    // Attention core
    ctx_kernel<<<dim3(Bn * Hh, NSPLIT), thr>>>(k, v, ctxp);
    att_kernel<<<dim3(Ln / 256, Bn * Hh), thr>>>(ctxp, q, att);
    // Reprojection + residual
    gemm_nn<<<dim3(32, 4, 8), thr>>>(Wr, br, att, z, z1, 512, 512, 0);
    // LN1 (in-place, channel-first)
    ln_kernel<<<Bn * (Ln / 32), thr>>>(z, z, g1, be1);
    // FFN
    gemm_nn<<<dim3(32, 8, 8), thr>>>(W1, b1, z, h, nullptr, 1024, 512, 1);
    gemm_nn<<<dim3(32, 4, 8), thr>>>(W2, b2, h, y, nullptr, 512, 1024, 0);
    // LN2 -> final output (channel-first already matches [B, C, L])
    ln_kernel<<<Bn * (Ln / 32), thr>>>(y, (float*)d_out, g2, be2);
}

// round 4
// speedup vs baseline: 1.8798x; 1.8798x over previous
#include <cuda_runtime.h>
#include <cuda_bf16.h>
#include <cstdint>

// Problem constants
#define Bn  8
#define Cc  512
#define Ln  4096
#define Hh  8
#define Dh  64
#define NSPLIT 4

// ---------------------------------------------------------------------------
// Scratch
// fp32: q,k,v,att,z,y (6 x 16777216), h (33554432), ctxp (1048576)
// ---------------------------------------------------------------------------
__device__ float g_scratch[135266304];
// bf16 converted/pre-tiled operands
__device__ __nv_bfloat16 g_bf[205520896];

// bf16 element offsets into g_bf
#define OFF_Z1C  0ull
#define OFF_Z2C  33554432ull
#define OFF_ATTC 67108864ull
#define OFF_ZC   100663296ull
#define OFF_HC   134217728ull
#define OFF_WQ   201326592ull
#define OFF_WK   201850880ull
#define OFF_WV   202375168ull
#define OFF_WR   202899456ull
#define OFF_W1   203423744ull
#define OFF_W2   204472320ull

// ---------------------------------------------------------------------------
// Helpers
// ---------------------------------------------------------------------------
__device__ __forceinline__ uint32_t smem_u32(const void* p) {
    uint32_t a;
    asm("{ .reg .u64 t; cvta.to.shared.u64 t, %1; cvt.u32.u64 %0, t; }"
        : "=r"(a) : "l"(p));
    return a;
}
__device__ __host__ __forceinline__ uint32_t swz128(uint32_t off) {
    return off ^ ((off >> 3) & 0x70);
}
__device__ __forceinline__ void cpasync16(uint32_t d, const void* s) {
    asm volatile("cp.async.cg.shared.global [%0], [%1], 16;" :: "r"(d), "l"(s));
}
#define CP_COMMIT() asm volatile("cp.async.commit_group;" ::: "memory")
#define CP_WAIT(N)  asm volatile("cp.async.wait_group " #N ";" ::: "memory")

#define LDSM4(R, ADDR) \
    asm volatile("ldmatrix.sync.aligned.m8n8.x4.shared.b16 {%0,%1,%2,%3}, [%4];" \
        : "=r"((R)[0]), "=r"((R)[1]), "=r"((R)[2]), "=r"((R)[3]) : "r"(ADDR))

#define MMA16816(C, A, Bv) \
    asm volatile("mma.sync.aligned.m16n8k16.row.col.f32.bf16.bf16.f32 " \
        "{%0,%1,%2,%3}, {%4,%5,%6,%7}, {%8,%9}, {%0,%1,%2,%3};" \
        : "+f"((C)[0]), "+f"((C)[1]), "+f"((C)[2]), "+f"((C)[3]) \
        : "r"((A)[0]), "r"((A)[1]), "r"((A)[2]), "r"((A)[3]), \
          "r"((Bv)[0]), "r"((Bv)[1]))

// ---------------------------------------------------------------------------
// Convert W [M,K] fp32 -> pre-tiled swizzled bf16 hi/lo blocks
// block per (mt, kc): [hi 128x64 swz 16KB][lo 16KB]; grid (K/64, M/128)
// ---------------------------------------------------------------------------
__global__ __launch_bounds__(256) void conv_w(
    const float* __restrict__ src, __nv_bfloat16* __restrict__ dstb, int K)
{
    int kc = blockIdx.x, mt = blockIdx.y;
    int NC = K >> 6;
    char* db = (char*)(dstb + ((size_t)(mt * NC + kc)) * 16384);
    const float* sb = src + ((size_t)mt * 128) * K + kc * 64;
    for (int it = 0; it < 4; it++) {
        int u = threadIdx.x + 256 * it;   // 0..1023
        int r = u >> 3, g = u & 7;        // row 0..127, group of 8 cols
        float x0[8];
        #pragma unroll
        for (int q = 0; q < 2; q++) {
            float4 v = *(const float4*)(sb + (size_t)r * K + g * 8 + q * 4);
            x0[q*4+0]=v.x; x0[q*4+1]=v.y; x0[q*4+2]=v.z; x0[q*4+3]=v.w;
        }
        uint32_t hw[4], lw[4];
        #pragma unroll
        for (int q = 0; q < 4; q++) {
            __nv_bfloat16 h0 = __float2bfloat16(x0[2*q]);
            __nv_bfloat16 h1 = __float2bfloat16(x0[2*q+1]);
            __nv_bfloat16 l0 = __float2bfloat16(x0[2*q]   - __bfloat162float(h0));
            __nv_bfloat16 l1 = __float2bfloat16(x0[2*q+1] - __bfloat162float(h1));
            hw[q] = (uint32_t)__bfloat16_as_ushort(h0) | ((uint32_t)__bfloat16_as_ushort(h1) << 16);
            lw[q] = (uint32_t)__bfloat16_as_ushort(l0) | ((uint32_t)__bfloat16_as_ushort(l1) << 16);
        }
        uint32_t sw = swz128((uint32_t)r * 128 + g * 16);
        *(uint4*)(db + sw)         = make_uint4(hw[0], hw[1], hw[2], hw[3]);
        *(uint4*)(db + 16384 + sw) = make_uint4(lw[0], lw[1], lw[2], lw[3]);
    }
}

// ---------------------------------------------------------------------------
// Convert+transpose X [B,K,L] fp32 -> blocks per (b, lt256, kc):
// [hi 256x64 swz 32KB][lo 32KB], rows = l, cols = k. grid (K/64, 16, B)
// ---------------------------------------------------------------------------
__global__ __launch_bounds__(256) void conv_x(
    const float* __restrict__ src, __nv_bfloat16* __restrict__ dstb, int K)
{
    int kc = blockIdx.x, lt = blockIdx.y, b = blockIdx.z;
    int NC = K >> 6;
    __shared__ float sm[32][264];
    const float* sb = src + ((size_t)b * K + kc * 64) * Ln + (size_t)lt * 256;
    char* db = (char*)(dstb + (((size_t)b * 16 + lt) * NC + kc) * 32768);
    int t = threadIdx.x;
    for (int p = 0; p < 2; p++) {
        __syncthreads();
        #pragma unroll
        for (int i = 0; i < 8; i++) {
            int u = t + 256 * i;     // 0..2047
            int kr = u >> 6;         // 0..31
            int lc = u & 63;         // float4 index in l
            float4 v = *(const float4*)(sb + ((size_t)(p * 32 + kr)) * Ln + lc * 4);
            sm[kr][lc*4+0]=v.x; sm[kr][lc*4+1]=v.y; sm[kr][lc*4+2]=v.z; sm[kr][lc*4+3]=v.w;
        }
        __syncthreads();
        #pragma unroll
        for (int g = 0; g < 4; g++) {
            float x0[8];
            #pragma unroll
            for (int j = 0; j < 8; j++) x0[j] = sm[g*8+j][t];
            uint32_t hw[4], lw[4];
            #pragma unroll
            for (int q = 0; q < 4; q++) {
                __nv_bfloat16 h0 = __float2bfloat16(x0[2*q]);
                __nv_bfloat16 h1 = __float2bfloat16(x0[2*q+1]);
                __nv_bfloat16 l0 = __float2bfloat16(x0[2*q]   - __bfloat162float(h0));
                __nv_bfloat16 l1 = __float2bfloat16(x0[2*q+1] - __bfloat162float(h1));
                hw[q] = (uint32_t)__bfloat16_as_ushort(h0) | ((uint32_t)__bfloat16_as_ushort(h1) << 16);
                lw[q] = (uint32_t)__bfloat16_as_ushort(l0) | ((uint32_t)__bfloat16_as_ushort(l1) << 16);
            }
            uint32_t sw = swz128((uint32_t)t * 128 + (p * 32 + g * 8) * 2);
            *(uint4*)(db + sw)         = make_uint4(hw[0], hw[1], hw[2], hw[3]);
            *(uint4*)(db + 32768 + sw) = make_uint4(lw[0], lw[1], lw[2], lw[3]);
        }
    }
}

// ---------------------------------------------------------------------------
// Warp-MMA bf16x3 GEMM: Out[b,m,l] = sum_k W[m,k] X[b,k,l] (+bias)(+Res)(ELU)
// CTA tile 128(m) x 128(l), K-chunk 64, 8 warps of 64x32, cp.async double buf.
// grid (M/128, L/128, B), 256 threads, dynamic smem 128KB.
// ---------------------------------------------------------------------------
__global__ __launch_bounds__(256, 1) void gemm_wm(
    const __nv_bfloat16* __restrict__ Wc, const float* __restrict__ bias,
    const __nv_bfloat16* __restrict__ Xc, float* __restrict__ Out,
    const float* __restrict__ Res, int M, int K, int act)
{
    extern __shared__ __align__(1024) char smem[];
    const int NC = K >> 6;
    int tid = threadIdx.x, wid = tid >> 5, lane = tid & 31;
    int mt = blockIdx.x, lt = blockIdx.y, b = blockIdx.z;
    int wm = wid >> 2, wn = wid & 3;          // warp: m-half (0..1), n-quarter (0..3)
    int sub = lane >> 3, r = lane & 7;

    // Source blocks (pre-swizzled): A per (mt,kc): 32KB (hi 16K + lo 16K)
    const char* Abase = (const char*)Wc + ((size_t)mt * NC) * 32768;
    // B per (b,lt256,kc): 64KB (hi 32K + lo 32K); our CTA uses a 16KB half of each
    int lt256 = lt >> 1, half = lt & 1;
    const char* Bbase = (const char*)Xc + (((size_t)b * 16 + lt256) * NC) * 65536
                        + (size_t)half * 16384;

    uint32_t sbase = smem_u32(smem);

    // ldmatrix per-lane address components
    // A x4 tile i: mats (m0-7,k0-7),(m8-15,k0-7),(m0-7,k8-15),(m8-15,k8-15)
    uint32_t aRow[4], aMask[4];
    int kaddA = (sub >> 1) * 16;
    #pragma unroll
    for (int i = 0; i < 4; i++) {
        uint32_t row = wm * 64 + i * 16 + (sub & 1) * 8 + r;
        aRow[i] = row * 128;
        aMask[i] = (aRow[i] >> 3) & 0x70;
    }
    // B x4 group j: mats (n0-7,k0-7),(n0-7,k8-15),(n8-15,k0-7),(n8-15,k8-15)
    uint32_t bRow[2], bMask[2];
    int kaddB = (sub & 1) * 16;
    #pragma unroll
    for (int j = 0; j < 2; j++) {
        uint32_t row = wn * 32 + j * 16 + (sub >> 1) * 8 + r;
        bRow[j] = row * 128;
        bMask[j] = (bRow[j] >> 3) & 0x70;
    }

    float acc[4][4][4];
    #pragma unroll
    for (int i = 0; i < 4; i++)
        #pragma unroll
        for (int j = 0; j < 4; j++)
            #pragma unroll
            for (int q = 0; q < 4; q++) acc[i][j][q] = 0.f;

    // Stage loader: [Ahi 16K][Alo 16K][Bhi 16K][Blo 16K] per 64KB stage
    auto load_stage = [&](int kc, int s) {
        uint32_t S = sbase + (uint32_t)s * 65536;
        const char* ah = Abase + (size_t)kc * 32768;
        const char* bh = Bbase + (size_t)kc * 65536;
        #pragma unroll
        for (int q = 0; q < 4; q++) {
            uint32_t off = (uint32_t)tid * 64 + q * 16;
            cpasync16(S + off,          ah + off);
            cpasync16(S + 16384 + off,  ah + 16384 + off);
            cpasync16(S + 32768 + off,  bh + off);
            cpasync16(S + 49152 + off,  bh + 32768 + off);
        }
    };

    load_stage(0, 0);
    CP_COMMIT();

    for (int c = 0; c < NC; c++) {
        if (c + 1 < NC) {
            load_stage(c + 1, (c + 1) & 1);
            CP_COMMIT();
            CP_WAIT(1);
        } else {
            CP_WAIT(0);
        }
        __syncthreads();

        uint32_t S = sbase + (uint32_t)(c & 1) * 65536;
        #pragma unroll
        for (int kk = 0; kk < 4; kk++) {
            int kb = kk * 32;
            uint32_t a_hi[16], a_lo[16], bb[8];
            // A hi + B hi
            #pragma unroll
            for (int i = 0; i < 4; i++)
                LDSM4(&a_hi[i * 4], S + aRow[i] + (uint32_t)((kaddA + kb) ^ aMask[i]));
            #pragma unroll
            for (int j = 0; j < 2; j++)
                LDSM4(&bb[j * 4], S + 32768 + bRow[j] + (uint32_t)((kaddB + kb) ^ bMask[j]));
            #pragma unroll
            for (int mi = 0; mi < 4; mi++)
                #pragma unroll
                for (int nj = 0; nj < 4; nj++)
                    MMA16816(acc[mi][nj], &a_hi[mi * 4], &bb[nj * 2]);
            // A lo x B hi
            #pragma unroll
            for (int i = 0; i < 4; i++)
                LDSM4(&a_lo[i * 4], S + 16384 + aRow[i] + (uint32_t)((kaddA + kb) ^ aMask[i]));
            #pragma unroll
            for (int mi = 0; mi < 4; mi++)
                #pragma unroll
                for (int nj = 0; nj < 4; nj++)
                    MMA16816(acc[mi][nj], &a_lo[mi * 4], &bb[nj * 2]);
            // A hi x B lo
            #pragma unroll
            for (int j = 0; j < 2; j++)
                LDSM4(&bb[j * 4], S + 49152 + bRow[j] + (uint32_t)((kaddB + kb) ^ bMask[j]));
            #pragma unroll
            for (int mi = 0; mi < 4; mi++)
                #pragma unroll
                for (int nj = 0; nj < 4; nj++)
                    MMA16816(acc[mi][nj], &a_hi[mi * 4], &bb[nj * 2]);
        }
        __syncthreads();
    }

    // Epilogue
    int g = lane >> 2, tg = lane & 3;
    #pragma unroll
    for (int mi = 0; mi < 4; mi++) {
        #pragma unroll
        for (int h2 = 0; h2 < 2; h2++) {
            int m = mt * 128 + wm * 64 + mi * 16 + h2 * 8 + g;
            float bi = bias[m];
            size_t rowoff = ((size_t)b * M + m) * Ln + (size_t)lt * 128 + wn * 32;
            #pragma unroll
            for (int nj = 0; nj < 4; nj++) {
                int col = nj * 8 + 2 * tg;
                float v0 = acc[mi][nj][h2 * 2 + 0] + bi;
                float v1 = acc[mi][nj][h2 * 2 + 1] + bi;
                if (Res) {
                    float2 r2 = *(const float2*)(Res + rowoff + col);
                    v0 += r2.x; v1 += r2.y;
                }
                if (act) {
                    v0 = v0 > 0.f ? v0 : expm1f(v0);
                    v1 = v1 > 0.f ? v1 : expm1f(v1);
                }
                *(float2*)(Out + rowoff + col) = make_float2(v0, v1);
            }
        }
    }
}

// ---------------------------------------------------------------------------
// Softmax over length (contiguous Ln rows)
// ---------------------------------------------------------------------------
__global__ __launch_bounds__(256) void softmax_len(float* __restrict__ data)
{
    __shared__ float red[256];
    float* p = data + (size_t)blockIdx.x * Ln;
    int t = threadIdx.x;
    float v[16];
    float m = -1e30f;
    #pragma unroll
    for (int i = 0; i < 16; i++) { v[i] = p[t + 256 * i]; m = fmaxf(m, v[i]); }
    red[t] = m; __syncthreads();
    for (int off = 128; off > 0; off >>= 1) {
        if (t < off) red[t] = fmaxf(red[t], red[t + off]);
        __syncthreads();
    }
    m = red[0];
    __syncthreads();
    float s = 0.f;
    #pragma unroll
    for (int i = 0; i < 16; i++) { v[i] = __expf(v[i] - m); s += v[i]; }
    red[t] = s; __syncthreads();
    for (int off = 128; off > 0; off >>= 1) {
        if (t < off) red[t] += red[t + off];
        __syncthreads();
    }
    float inv = 1.f / red[0];
    #pragma unroll
    for (int i = 0; i < 16; i++) p[t + 256 * i] = v[i] * inv;
}

// ---------------------------------------------------------------------------
// Softmax over head-channel dim (Dh=64, stride Ln)
// ---------------------------------------------------------------------------
__global__ __launch_bounds__(256) void softmax_head(float* __restrict__ q)
{
    int l = blockIdx.x * 256 + threadIdx.x;
    int bh = blockIdx.y;
    float* base = q + (size_t)bh * Dh * Ln + l;
    float v[64];
    float m = -1e30f;
    #pragma unroll
    for (int d = 0; d < 64; d++) { v[d] = base[(size_t)d * Ln]; m = fmaxf(m, v[d]); }
    float s = 0.f;
    #pragma unroll
    for (int d = 0; d < 64; d++) { v[d] = __expf(v[d] - m); s += v[d]; }
    float inv = 1.f / s;
    #pragma unroll
    for (int d = 0; d < 64; d++) base[(size_t)d * Ln] = v[d] * inv;
}

// ---------------------------------------------------------------------------
// ctx partials
// ---------------------------------------------------------------------------
__global__ __launch_bounds__(256) void ctx_kernel(
    const float* __restrict__ kk, const float* __restrict__ vv,
    float* __restrict__ ctxp)
{
    int bh = blockIdx.x;
    int sp = blockIdx.y;
    const float* kb = kk + (size_t)bh * Dh * Ln;
    const float* vb = vv + (size_t)bh * Dh * Ln;

    __shared__ float ks[64][33];
    __shared__ float vs[64][33];

    int tid = threadIdx.x;
    int lt = tid & 31, dr = tid >> 5;
    int tx = tid & 15, ty = tid >> 4;

    float acc[4][4];
    #pragma unroll
    for (int i = 0; i < 4; i++)
        #pragma unroll
        for (int j = 0; j < 4; j++) acc[i][j] = 0.f;

    int lbeg = sp * (Ln / NSPLIT);
    int lend = lbeg + (Ln / NSPLIT);
    for (int l0 = lbeg; l0 < lend; l0 += 32) {
        __syncthreads();
        #pragma unroll
        for (int r = 0; r < 8; r++) {
            int dk = dr + 8 * r;
            ks[dk][lt] = kb[(size_t)dk * Ln + l0 + lt];
            vs[dk][lt] = vb[(size_t)dk * Ln + l0 + lt];
        }
        __syncthreads();
        #pragma unroll
        for (int l2 = 0; l2 < 32; l2++) {
            float av[4], bw[4];
            #pragma unroll
            for (int i = 0; i < 4; i++) av[i] = ks[ty * 4 + i][l2];
            #pragma unroll
            for (int j = 0; j < 4; j++) bw[j] = vs[tx * 4 + j][l2];
            #pragma unroll
            for (int i = 0; i < 4; i++)
                #pragma unroll
                for (int j = 0; j < 4; j++)
                    acc[i][j] += av[i] * bw[j];
        }
    }
    #pragma unroll
    for (int i = 0; i < 4; i++)
        #pragma unroll
        for (int j = 0; j < 4; j++) {
            int dk = ty * 4 + i, dv = tx * 4 + j;
            ctxp[(((size_t)sp * 64 + bh) * 64 + dk) * 64 + dv] = acc[i][j];
        }
}

// ---------------------------------------------------------------------------
// att = ctx^T applied to q
// ---------------------------------------------------------------------------
__global__ __launch_bounds__(256) void att_kernel(
    const float* __restrict__ ctxp, const float* __restrict__ q,
    float* __restrict__ att)
{
    int bh = blockIdx.y;
    __shared__ float cs[64][64];
    int tid = threadIdx.x;

    float4* cs4 = (float4*)cs;
    #pragma unroll
    for (int r = 0; r < 4; r++) {
        int idx = tid + 256 * r;
        float4 sum = make_float4(0.f, 0.f, 0.f, 0.f);
        #pragma unroll
        for (int s = 0; s < NSPLIT; s++) {
            const float4* p = (const float4*)(ctxp + ((size_t)s * 64 + bh) * 4096);
            float4 t = p[idx];
            sum.x += t.x; sum.y += t.y; sum.z += t.z; sum.w += t.w;
        }
        cs4[idx] = sum;
    }
    __syncthreads();

    int l = blockIdx.x * 256 + tid;
    const float* qb = q + (size_t)bh * Dh * Ln + l;
    float acc[64];
    #pragma unroll
    for (int d = 0; d < 64; d++) acc[d] = 0.f;

    #pragma unroll 4
    for (int dk = 0; dk < 64; dk++) {
        float qv = qb[(size_t)dk * Ln];
        #pragma unroll
        for (int j = 0; j < 16; j++) {
            float4 c4 = *(const float4*)&cs[dk][j * 4];
            acc[4 * j + 0] += c4.x * qv;
            acc[4 * j + 1] += c4.y * qv;
            acc[4 * j + 2] += c4.z * qv;
            acc[4 * j + 3] += c4.w * qv;
        }
    }
    float* ab = att + (size_t)bh * Dh * Ln + l;
    #pragma unroll
    for (int dv = 0; dv < 64; dv++) ab[(size_t)dv * Ln] = acc[dv];
}

// ---------------------------------------------------------------------------
// Channel LayerNorm over C=512 (stride Ln)
// ---------------------------------------------------------------------------
__global__ __launch_bounds__(256) void ln_kernel(
    const float* __restrict__ in, float* __restrict__ out,
    const float* __restrict__ g, const float* __restrict__ be)
{
    __shared__ float ss[8][32], sq[8][32], smean[32], srstd[32];
    int blk = blockIdx.x;
    int b = blk >> 7;
    int li = threadIdx.x & 31;
    int l = ((blk & 127) << 5) + li;
    int r = threadIdx.x >> 5;
    const float* base = in + (size_t)b * Cc * Ln + l;

    float s = 0.f, s2 = 0.f;
    #pragma unroll
    for (int k2 = 0; k2 < 64; k2++) {
        int c = r * 64 + k2;
        float x = base[(size_t)c * Ln];
        s += x; s2 += x * x;
    }
    ss[r][li] = s; sq[r][li] = s2;
    __syncthreads();
    if (r == 0) {
        float ts = ss[0][li], t2 = sq[0][li];
        #pragma unroll
        for (int rr = 1; rr < 8; rr++) { ts += ss[rr][li]; t2 += sq[rr][li]; }
        float mean = ts * (1.f / 512.f);
        float var = t2 * (1.f / 512.f) - mean * mean;
        smean[li] = mean;
        srstd[li] = rsqrtf(var + 1e-5f);
    }
    __syncthreads();
    float mean = smean[li], rstd = srstd[li];
    float* ob = out + (size_t)b * Cc * Ln + l;
    #pragma unroll
    for (int k2 = 0; k2 < 64; k2++) {
        int c = r * 64 + k2;
        float x = base[(size_t)c * Ln];
        ob[(size_t)c * Ln] = (x - mean) * rstd * g[c] + be[c];
    }
}

// ---------------------------------------------------------------------------
extern "C" void kernel_launch(void* const* d_in, const int* in_sizes, int n_in,
                              void* d_out, int out_size)
{
    const float* z1  = (const float*)d_in[0];
    const float* z2  = (const float*)d_in[1];
    const float* Wq  = (const float*)d_in[2];
    const float* bq  = (const float*)d_in[3];
    const float* Wk  = (const float*)d_in[4];
    const float* bkb = (const float*)d_in[5];
    const float* Wv  = (const float*)d_in[6];
    const float* bv  = (const float*)d_in[7];
    const float* Wr  = (const float*)d_in[8];
    const float* br  = (const float*)d_in[9];
    const float* g1  = (const float*)d_in[10];
    const float* be1 = (const float*)d_in[11];
    const float* W1  = (const float*)d_in[12];
    const float* b1  = (const float*)d_in[13];
    const float* W2  = (const float*)d_in[14];
    const float* b2  = (const float*)d_in[15];
    const float* g2  = (const float*)d_in[16];
    const float* be2 = (const float*)d_in[17];

    float* fs = nullptr;
    cudaGetSymbolAddress((void**)&fs, g_scratch);
    __nv_bfloat16* bf = nullptr;
    cudaGetSymbolAddress((void**)&bf, g_bf);

    const size_t SZ = (size_t)Bn * Cc * Ln;   // 16777216
    float* q    = fs;
    float* k    = fs + SZ;
    float* v    = fs + 2 * SZ;
    float* att  = fs + 3 * SZ;
    float* z    = fs + 4 * SZ;
    float* y    = fs + 5 * SZ;
    float* h    = fs + 6 * SZ;                // 2*SZ
    float* ctxp = fs + 8 * SZ;

    const int GEMM_SMEM = 131072;
    cudaFuncSetAttribute(gemm_wm, cudaFuncAttributeMaxDynamicSharedMemorySize, GEMM_SMEM);

    dim3 thr(256);
    // Weight conversions
    conv_w<<<dim3(8, 4), thr>>>(Wq, bf + OFF_WQ, 512);
    conv_w<<<dim3(8, 4), thr>>>(Wk, bf + OFF_WK, 512);
    conv_w<<<dim3(8, 4), thr>>>(Wv, bf + OFF_WV, 512);
    conv_w<<<dim3(8, 4), thr>>>(Wr, bf + OFF_WR, 512);
    conv_w<<<dim3(8, 8), thr>>>(W1, bf + OFF_W1, 512);
    conv_w<<<dim3(16, 4), thr>>>(W2, bf + OFF_W2, 1024);

    // Input conversions
    conv_x<<<dim3(8, 16, 8), thr>>>(z1, bf + OFF_Z1C, 512);
    conv_x<<<dim3(8, 16, 8), thr>>>(z2, bf + OFF_Z2C, 512);

    // Projections (warp-MMA bf16x3)
    gemm_wm<<<dim3(4, 32, 8), 256, GEMM_SMEM>>>(bf + OFF_WQ, bq,  bf + OFF_Z1C, q, nullptr, 512, 512, 0);
    gemm_wm<<<dim3(4, 32, 8), 256, GEMM_SMEM>>>(bf + OFF_WK, bkb, bf + OFF_Z2C, k, nullptr, 512, 512, 0);
    gemm_wm<<<dim3(4, 32, 8), 256, GEMM_SMEM>>>(bf + OFF_WV, bv,  bf + OFF_Z2C, v, nullptr, 512, 512, 0);

    // Softmaxes
    softmax_len<<<Bn * Cc, thr>>>(k);
    softmax_head<<<dim3(Ln / 256, Bn * Hh), thr>>>(q);

    // Attention core
    ctx_kernel<<<dim3(Bn * Hh, NSPLIT), thr>>>(k, v, ctxp);
    att_kernel<<<dim3(Ln / 256, Bn * Hh), thr>>>(ctxp, q, att);

    // Reprojection + residual
    conv_x<<<dim3(8, 16, 8), thr>>>(att, bf + OFF_ATTC, 512);
    gemm_wm<<<dim3(4, 32, 8), 256, GEMM_SMEM>>>(bf + OFF_WR, br, bf + OFF_ATTC, z, z1, 512, 512, 0);

    // LN1
    ln_kernel<<<Bn * (Ln / 32), thr>>>(z, z, g1, be1);

    // FFN
    conv_x<<<dim3(8, 16, 8), thr>>>(z, bf + OFF_ZC, 512);
    gemm_wm<<<dim3(8, 32, 8), 256, GEMM_SMEM>>>(bf + OFF_W1, b1, bf + OFF_ZC, h, nullptr, 1024, 512, 1);
    conv_x<<<dim3(16, 16, 8), thr>>>(h, bf + OFF_HC, 1024);
    gemm_wm<<<dim3(4, 32, 8), 256, GEMM_SMEM>>>(bf + OFF_W2, b2, bf + OFF_HC, y, nullptr, 512, 1024, 0);

    // LN2 -> output
    ln_kernel<<<Bn * (Ln / 32), thr>>>(y, (float*)d_out, g2, be2);
}

// round 5
// speedup vs baseline: 3.7294x; 1.9840x over previous
#include <cuda_runtime.h>
#include <cuda_fp16.h>
#include <cstdint>

// Problem constants
#define Bn  8
#define Cc  512
#define Ln  4096
#define Hh  8
#define Dh  64
#define NSPLIT 4

// ---------------------------------------------------------------------------
// Scratch
// fp32: q,k,v,att,z,y (6 x 16777216), h (33554432), ctxp (1048576)
// ---------------------------------------------------------------------------
__device__ float g_scratch[135266304];
// fp16 converted/pre-tiled operands (single plane)
__device__ __half g_hf[102760448];

// half-element offsets into g_hf
#define OFF_Z1C  0ull
#define OFF_Z2C  16777216ull
#define OFF_ATTC 33554432ull
#define OFF_ZC   50331648ull
#define OFF_HC   67108864ull
#define OFF_WQ   100663296ull
#define OFF_WK   100925440ull
#define OFF_WV   101187584ull
#define OFF_WR   101449728ull
#define OFF_W1   101711872ull
#define OFF_W2   102236160ull

// ---------------------------------------------------------------------------
// Helpers
// ---------------------------------------------------------------------------
__device__ __forceinline__ uint32_t smem_u32(const void* p) {
    uint32_t a;
    asm("{ .reg .u64 t; cvta.to.shared.u64 t, %1; cvt.u32.u64 %0, t; }"
        : "=r"(a) : "l"(p));
    return a;
}
__device__ __host__ __forceinline__ uint32_t swz128(uint32_t off) {
    return off ^ ((off >> 3) & 0x70);
}
__device__ __forceinline__ void cpasync16(uint32_t d, const void* s) {
    asm volatile("cp.async.cg.shared.global [%0], [%1], 16;" :: "r"(d), "l"(s));
}
#define CP_COMMIT() asm volatile("cp.async.commit_group;" ::: "memory")
#define CP_WAIT(N)  asm volatile("cp.async.wait_group " #N ";" ::: "memory")

#define LDSM4(R, ADDR) \
    asm volatile("ldmatrix.sync.aligned.m8n8.x4.shared.b16 {%0,%1,%2,%3}, [%4];" \
        : "=r"((R)[0]), "=r"((R)[1]), "=r"((R)[2]), "=r"((R)[3]) : "r"(ADDR))

#define MMA16816(C, A, Bv) \
    asm volatile("mma.sync.aligned.m16n8k16.row.col.f32.f16.f16.f32 " \
        "{%0,%1,%2,%3}, {%4,%5,%6,%7}, {%8,%9}, {%0,%1,%2,%3};" \
        : "+f"((C)[0]), "+f"((C)[1]), "+f"((C)[2]), "+f"((C)[3]) \
        : "r"((A)[0]), "r"((A)[1]), "r"((A)[2]), "r"((A)[3]), \
          "r"((Bv)[0]), "r"((Bv)[1]))

__device__ __forceinline__ uint32_t pack2h(float a, float b) {
    __half2 h = __floats2half2_rn(a, b);
    return *(uint32_t*)&h;
}

// ---------------------------------------------------------------------------
// Convert W [M,K] fp32 -> pre-tiled swizzled fp16 blocks
// block per (mt, kc): 128 rows(m) x 64 cols(k) fp16, 128B rows, SW128 = 16KB
// grid (K/64, M/128), 256 threads
// ---------------------------------------------------------------------------
__global__ __launch_bounds__(256) void conv_w(
    const float* __restrict__ src, __half* __restrict__ dstb, int K)
{
    int kc = blockIdx.x, mt = blockIdx.y;
    int NC = K >> 6;
    char* db = (char*)(dstb + ((size_t)(mt * NC + kc)) * 8192);
    const float* sb = src + ((size_t)mt * 128) * K + kc * 64;
    for (int it = 0; it < 4; it++) {
        int u = threadIdx.x + 256 * it;   // 0..1023
        int r = u >> 3, g = u & 7;        // row 0..127, group of 8 cols
        float x0[8];
        #pragma unroll
        for (int q = 0; q < 2; q++) {
            float4 v = *(const float4*)(sb + (size_t)r * K + g * 8 + q * 4);
            x0[q*4+0]=v.x; x0[q*4+1]=v.y; x0[q*4+2]=v.z; x0[q*4+3]=v.w;
        }
        uint4 w;
        w.x = pack2h(x0[0], x0[1]);
        w.y = pack2h(x0[2], x0[3]);
        w.z = pack2h(x0[4], x0[5]);
        w.w = pack2h(x0[6], x0[7]);
        uint32_t sw = swz128((uint32_t)r * 128 + g * 16);
        *(uint4*)(db + sw) = w;
    }
}

// ---------------------------------------------------------------------------
// Convert+transpose X [B,K,L] fp32 -> blocks per (b, lt256, kc):
// 256 rows(l) x 64 cols(k) fp16, 128B rows, SW128 = 32KB. grid (K/64, 16, B)
// ---------------------------------------------------------------------------
__global__ __launch_bounds__(256) void conv_x(
    const float* __restrict__ src, __half* __restrict__ dstb, int K)
{
    int kc = blockIdx.x, lt = blockIdx.y, b = blockIdx.z;
    int NC = K >> 6;
    __shared__ float sm[32][264];
    const float* sb = src + ((size_t)b * K + kc * 64) * Ln + (size_t)lt * 256;
    char* db = (char*)(dstb + (((size_t)b * 16 + lt) * NC + kc) * 16384);
    int t = threadIdx.x;
    for (int p = 0; p < 2; p++) {
        __syncthreads();
        #pragma unroll
        for (int i = 0; i < 8; i++) {
            int u = t + 256 * i;     // 0..2047
            int kr = u >> 6;         // 0..31
            int lc = u & 63;         // float4 index in l
            float4 v = *(const float4*)(sb + ((size_t)(p * 32 + kr)) * Ln + lc * 4);
            sm[kr][lc*4+0]=v.x; sm[kr][lc*4+1]=v.y; sm[kr][lc*4+2]=v.z; sm[kr][lc*4+3]=v.w;
        }
        __syncthreads();
        #pragma unroll
        for (int g = 0; g < 4; g++) {
            float x0[8];
            #pragma unroll
            for (int j = 0; j < 8; j++) x0[j] = sm[g*8+j][t];
            uint4 w;
            w.x = pack2h(x0[0], x0[1]);
            w.y = pack2h(x0[2], x0[3]);
            w.z = pack2h(x0[4], x0[5]);
            w.w = pack2h(x0[6], x0[7]);
            uint32_t sw = swz128((uint32_t)t * 128 + (p * 32 + g * 8) * 2);
            *(uint4*)(db + sw) = w;
        }
    }
}

// ---------------------------------------------------------------------------
// Warp-MMA fp16 GEMM: Out[b,m,l] = sum_k W[m,k] X[b,k,l] (+bias)(+Res)(ELU)
// CTA tile 128(m) x 128(l), K-chunk 64, 8 warps of 64x32, cp.async double buf.
// grid (M/128, L/128, B), 256 threads, dynamic smem 64KB, 2 CTAs/SM.
// ---------------------------------------------------------------------------
__global__ __launch_bounds__(256, 2) void gemm_wm(
    const __half* __restrict__ Wc, const float* __restrict__ bias,
    const __half* __restrict__ Xc, float* __restrict__ Out,
    const float* __restrict__ Res, int M, int K, int act)
{
    extern __shared__ __align__(1024) char smem[];
    const int NC = K >> 6;
    int tid = threadIdx.x, wid = tid >> 5, lane = tid & 31;
    int mt = blockIdx.x, lt = blockIdx.y, b = blockIdx.z;
    int wm = wid >> 2, wn = wid & 3;          // warp: m-half (0..1), n-quarter (0..3)
    int sub = lane >> 3, r = lane & 7;

    // A block per (mt,kc): 16KB
    const char* Abase = (const char*)Wc + ((size_t)mt * NC) * 16384;
    // B block per (b,lt256,kc): 32KB; CTA uses a 16KB half (128 l rows)
    int lt256 = lt >> 1, half = lt & 1;
    const char* Bbase = (const char*)Xc + (((size_t)b * 16 + lt256) * NC) * 32768
                        + (size_t)half * 16384;

    uint32_t sbase = smem_u32(smem);

    // ldmatrix per-lane address components
    uint32_t aRow[4], aMask[4];
    int kaddA = (sub >> 1) * 16;
    #pragma unroll
    for (int i = 0; i < 4; i++) {
        uint32_t row = wm * 64 + i * 16 + (sub & 1) * 8 + r;
        aRow[i] = row * 128;
        aMask[i] = (aRow[i] >> 3) & 0x70;
    }
    uint32_t bRow[2], bMask[2];
    int kaddB = (sub & 1) * 16;
    #pragma unroll
    for (int j = 0; j < 2; j++) {
        uint32_t row = wn * 32 + j * 16 + (sub >> 1) * 8 + r;
        bRow[j] = row * 128;
        bMask[j] = (bRow[j] >> 3) & 0x70;
    }

    float acc[4][4][4];
    #pragma unroll
    for (int i = 0; i < 4; i++)
        #pragma unroll
        for (int j = 0; j < 4; j++)
            #pragma unroll
            for (int q = 0; q < 4; q++) acc[i][j][q] = 0.f;

    // Stage: [A 16K][B 16K] = 32KB
    auto load_stage = [&](int kc, int s) {
        uint32_t S = sbase + (uint32_t)s * 32768;
        const char* ah = Abase + (size_t)kc * 16384;
        const char* bh = Bbase + (size_t)kc * 32768;
        #pragma unroll
        for (int q = 0; q < 4; q++) {
            uint32_t off = (uint32_t)tid * 64 + q * 16;
            cpasync16(S + off,         ah + off);
            cpasync16(S + 16384 + off, bh + off);
        }
    };

    load_stage(0, 0);
    CP_COMMIT();

    for (int c = 0; c < NC; c++) {
        if (c + 1 < NC) {
            load_stage(c + 1, (c + 1) & 1);
            CP_COMMIT();
            CP_WAIT(1);
        } else {
            CP_WAIT(0);
        }
        __syncthreads();

        uint32_t S = sbase + (uint32_t)(c & 1) * 32768;
        #pragma unroll
        for (int kk = 0; kk < 4; kk++) {
            int kb = kk * 32;
            uint32_t aa[16], bb[8];
            #pragma unroll
            for (int i = 0; i < 4; i++)
                LDSM4(&aa[i * 4], S + aRow[i] + (uint32_t)((kaddA + kb) ^ aMask[i]));
            #pragma unroll
            for (int j = 0; j < 2; j++)
                LDSM4(&bb[j * 4], S + 16384 + bRow[j] + (uint32_t)((kaddB + kb) ^ bMask[j]));
            #pragma unroll
            for (int mi = 0; mi < 4; mi++)
                #pragma unroll
                for (int nj = 0; nj < 4; nj++)
                    MMA16816(acc[mi][nj], &aa[mi * 4], &bb[nj * 2]);
        }
        __syncthreads();
    }

    // Epilogue
    int g = lane >> 2, tg = lane & 3;
    #pragma unroll
    for (int mi = 0; mi < 4; mi++) {
        #pragma unroll
        for (int h2 = 0; h2 < 2; h2++) {
            int m = mt * 128 + wm * 64 + mi * 16 + h2 * 8 + g;
            float bi = bias[m];
            size_t rowoff = ((size_t)b * M + m) * Ln + (size_t)lt * 128 + wn * 32;
            #pragma unroll
            for (int nj = 0; nj < 4; nj++) {
                int col = nj * 8 + 2 * tg;
                float v0 = acc[mi][nj][h2 * 2 + 0] + bi;
                float v1 = acc[mi][nj][h2 * 2 + 1] + bi;
                if (Res) {
                    float2 r2 = *(const float2*)(Res + rowoff + col);
                    v0 += r2.x; v1 += r2.y;
                }
                if (act) {
                    v0 = v0 > 0.f ? v0 : expm1f(v0);
                    v1 = v1 > 0.f ? v1 : expm1f(v1);
                }
                *(float2*)(Out + rowoff + col) = make_float2(v0, v1);
            }
        }
    }
}

// ---------------------------------------------------------------------------
// Softmax over length (contiguous Ln rows)
// ---------------------------------------------------------------------------
__global__ __launch_bounds__(256) void softmax_len(float* __restrict__ data)
{
    __shared__ float red[256];
    float* p = data + (size_t)blockIdx.x * Ln;
    int t = threadIdx.x;
    float v[16];
    float m = -1e30f;
    #pragma unroll
    for (int i = 0; i < 16; i++) { v[i] = p[t + 256 * i]; m = fmaxf(m, v[i]); }
    red[t] = m; __syncthreads();
    for (int off = 128; off > 0; off >>= 1) {
        if (t < off) red[t] = fmaxf(red[t], red[t + off]);
        __syncthreads();
    }
    m = red[0];
    __syncthreads();
    float s = 0.f;
    #pragma unroll
    for (int i = 0; i < 16; i++) { v[i] = __expf(v[i] - m); s += v[i]; }
    red[t] = s; __syncthreads();
    for (int off = 128; off > 0; off >>= 1) {
        if (t < off) red[t] += red[t + off];
        __syncthreads();
    }
    float inv = 1.f / red[0];
    #pragma unroll
    for (int i = 0; i < 16; i++) p[t + 256 * i] = v[i] * inv;
}

// ---------------------------------------------------------------------------
// Softmax over head-channel dim (Dh=64, stride Ln)
// ---------------------------------------------------------------------------
__global__ __launch_bounds__(256) void softmax_head(float* __restrict__ q)
{
    int l = blockIdx.x * 256 + threadIdx.x;
    int bh = blockIdx.y;
    float* base = q + (size_t)bh * Dh * Ln + l;
    float v[64];
    float m = -1e30f;
    #pragma unroll
    for (int d = 0; d < 64; d++) { v[d] = base[(size_t)d * Ln]; m = fmaxf(m, v[d]); }
    float s = 0.f;
    #pragma unroll
    for (int d = 0; d < 64; d++) { v[d] = __expf(v[d] - m); s += v[d]; }
    float inv = 1.f / s;
    #pragma unroll
    for (int d = 0; d < 64; d++) base[(size_t)d * Ln] = v[d] * inv;
}

// ---------------------------------------------------------------------------
// ctx partials
// ---------------------------------------------------------------------------
__global__ __launch_bounds__(256) void ctx_kernel(
    const float* __restrict__ kk, const float* __restrict__ vv,
    float* __restrict__ ctxp)
{
    int bh = blockIdx.x;
    int sp = blockIdx.y;
    const float* kb = kk + (size_t)bh * Dh * Ln;
    const float* vb = vv + (size_t)bh * Dh * Ln;

    __shared__ float ks[64][33];
    __shared__ float vs[64][33];

    int tid = threadIdx.x;
    int lt = tid & 31, dr = tid >> 5;
    int tx = tid & 15, ty = tid >> 4;

    float acc[4][4];
    #pragma unroll
    for (int i = 0; i < 4; i++)
        #pragma unroll
        for (int j = 0; j < 4; j++) acc[i][j] = 0.f;

    int lbeg = sp * (Ln / NSPLIT);
    int lend = lbeg + (Ln / NSPLIT);
    for (int l0 = lbeg; l0 < lend; l0 += 32) {
        __syncthreads();
        #pragma unroll
        for (int r = 0; r < 8; r++) {
            int dk = dr + 8 * r;
            ks[dk][lt] = kb[(size_t)dk * Ln + l0 + lt];
            vs[dk][lt] = vb[(size_t)dk * Ln + l0 + lt];
        }
        __syncthreads();
        #pragma unroll
        for (int l2 = 0; l2 < 32; l2++) {
            float av[4], bw[4];
            #pragma unroll
            for (int i = 0; i < 4; i++) av[i] = ks[ty * 4 + i][l2];
            #pragma unroll
            for (int j = 0; j < 4; j++) bw[j] = vs[tx * 4 + j][l2];
            #pragma unroll
            for (int i = 0; i < 4; i++)
                #pragma unroll
                for (int j = 0; j < 4; j++)
                    acc[i][j] += av[i] * bw[j];
        }
    }
    #pragma unroll
    for (int i = 0; i < 4; i++)
        #pragma unroll
        for (int j = 0; j < 4; j++) {
            int dk = ty * 4 + i, dv = tx * 4 + j;
            ctxp[(((size_t)sp * 64 + bh) * 64 + dk) * 64 + dv] = acc[i][j];
        }
}

// ---------------------------------------------------------------------------
// att = ctx^T applied to q
// ---------------------------------------------------------------------------
__global__ __launch_bounds__(256) void att_kernel(
    const float* __restrict__ ctxp, const float* __restrict__ q,
    float* __restrict__ att)
{
    int bh = blockIdx.y;
    __shared__ float cs[64][64];
    int tid = threadIdx.x;

    float4* cs4 = (float4*)cs;
    #pragma unroll
    for (int r = 0; r < 4; r++) {
        int idx = tid + 256 * r;
        float4 sum = make_float4(0.f, 0.f, 0.f, 0.f);
        #pragma unroll
        for (int s = 0; s < NSPLIT; s++) {
            const float4* p = (const float4*)(ctxp + ((size_t)s * 64 + bh) * 4096);
            float4 t = p[idx];
            sum.x += t.x; sum.y += t.y; sum.z += t.z; sum.w += t.w;
        }
        cs4[idx] = sum;
    }
    __syncthreads();

    int l = blockIdx.x * 256 + tid;
    const float* qb = q + (size_t)bh * Dh * Ln + l;
    float acc[64];
    #pragma unroll
    for (int d = 0; d < 64; d++) acc[d] = 0.f;

    #pragma unroll 4
    for (int dk = 0; dk < 64; dk++) {
        float qv = qb[(size_t)dk * Ln];
        #pragma unroll
        for (int j = 0; j < 16; j++) {
            float4 c4 = *(const float4*)&cs[dk][j * 4];
            acc[4 * j + 0] += c4.x * qv;
            acc[4 * j + 1] += c4.y * qv;
            acc[4 * j + 2] += c4.z * qv;
            acc[4 * j + 3] += c4.w * qv;
        }
    }
    float* ab = att + (size_t)bh * Dh * Ln + l;
    #pragma unroll
    for (int dv = 0; dv < 64; dv++) ab[(size_t)dv * Ln] = acc[dv];
}

// ---------------------------------------------------------------------------
// Channel LayerNorm over C=512 (stride Ln)
// ---------------------------------------------------------------------------
__global__ __launch_bounds__(256) void ln_kernel(
    const float* __restrict__ in, float* __restrict__ out,
    const float* __restrict__ g, const float* __restrict__ be)
{
    __shared__ float ss[8][32], sq[8][32], smean[32], srstd[32];
    int blk = blockIdx.x;
    int b = blk >> 7;
    int li = threadIdx.x & 31;
    int l = ((blk & 127) << 5) + li;
    int r = threadIdx.x >> 5;
    const float* base = in + (size_t)b * Cc * Ln + l;

    float s = 0.f, s2 = 0.f;
    #pragma unroll
    for (int k2 = 0; k2 < 64; k2++) {
        int c = r * 64 + k2;
        float x = base[(size_t)c * Ln];
        s += x; s2 += x * x;
    }
    ss[r][li] = s; sq[r][li] = s2;
    __syncthreads();
    if (r == 0) {
        float ts = ss[0][li], t2 = sq[0][li];
        #pragma unroll
        for (int rr = 1; rr < 8; rr++) { ts += ss[rr][li]; t2 += sq[rr][li]; }
        float mean = ts * (1.f / 512.f);
        float var = t2 * (1.f / 512.f) - mean * mean;
        smean[li] = mean;
        srstd[li] = rsqrtf(var + 1e-5f);
    }
    __syncthreads();
    float mean = smean[li], rstd = srstd[li];
    float* ob = out + (size_t)b * Cc * Ln + l;
    #pragma unroll
    for (int k2 = 0; k2 < 64; k2++) {
        int c = r * 64 + k2;
        float x = base[(size_t)c * Ln];
        ob[(size_t)c * Ln] = (x - mean) * rstd * g[c] + be[c];
    }
}

// ---------------------------------------------------------------------------
extern "C" void kernel_launch(void* const* d_in, const int* in_sizes, int n_in,
                              void* d_out, int out_size)
{
    const float* z1  = (const float*)d_in[0];
    const float* z2  = (const float*)d_in[1];
    const float* Wq  = (const float*)d_in[2];
    const float* bq  = (const float*)d_in[3];
    const float* Wk  = (const float*)d_in[4];
    const float* bkb = (const float*)d_in[5];
    const float* Wv  = (const float*)d_in[6];
    const float* bv  = (const float*)d_in[7];
    const float* Wr  = (const float*)d_in[8];
    const float* br  = (const float*)d_in[9];
    const float* g1  = (const float*)d_in[10];
    const float* be1 = (const float*)d_in[11];
    const float* W1  = (const float*)d_in[12];
    const float* b1  = (const float*)d_in[13];
    const float* W2  = (const float*)d_in[14];
    const float* b2  = (const float*)d_in[15];
    const float* g2  = (const float*)d_in[16];
    const float* be2 = (const float*)d_in[17];

    float* fs = nullptr;
    cudaGetSymbolAddress((void**)&fs, g_scratch);
    __half* hf = nullptr;
    cudaGetSymbolAddress((void**)&hf, g_hf);

    const size_t SZ = (size_t)Bn * Cc * Ln;   // 16777216
    float* q    = fs;
    float* k    = fs + SZ;
    float* v    = fs + 2 * SZ;
    float* att  = fs + 3 * SZ;
    float* z    = fs + 4 * SZ;
    float* y    = fs + 5 * SZ;
    float* h    = fs + 6 * SZ;                // 2*SZ
    float* ctxp = fs + 8 * SZ;

    const int GEMM_SMEM = 65536;
    cudaFuncSetAttribute(gemm_wm, cudaFuncAttributeMaxDynamicSharedMemorySize, GEMM_SMEM);

    dim3 thr(256);
    // Weight conversions
    conv_w<<<dim3(8, 4), thr>>>(Wq, hf + OFF_WQ, 512);
    conv_w<<<dim3(8, 4), thr>>>(Wk, hf + OFF_WK, 512);
    conv_w<<<dim3(8, 4), thr>>>(Wv, hf + OFF_WV, 512);
    conv_w<<<dim3(8, 4), thr>>>(Wr, hf + OFF_WR, 512);
    conv_w<<<dim3(8, 8), thr>>>(W1, hf + OFF_W1, 512);
    conv_w<<<dim3(16, 4), thr>>>(W2, hf + OFF_W2, 1024);

    // Input conversions
    conv_x<<<dim3(8, 16, 8), thr>>>(z1, hf + OFF_Z1C, 512);
    conv_x<<<dim3(8, 16, 8), thr>>>(z2, hf + OFF_Z2C, 512);

    // Projections (warp-MMA fp16)
    gemm_wm<<<dim3(4, 32, 8), 256, GEMM_SMEM>>>(hf + OFF_WQ, bq,  hf + OFF_Z1C, q, nullptr, 512, 512, 0);
    gemm_wm<<<dim3(4, 32, 8), 256, GEMM_SMEM>>>(hf + OFF_WK, bkb, hf + OFF_Z2C, k, nullptr, 512, 512, 0);
    gemm_wm<<<dim3(4, 32, 8), 256, GEMM_SMEM>>>(hf + OFF_WV, bv,  hf + OFF_Z2C, v, nullptr, 512, 512, 0);

    // Softmaxes
    softmax_len<<<Bn * Cc, thr>>>(k);
    softmax_head<<<dim3(Ln / 256, Bn * Hh), thr>>>(q);

    // Attention core
    ctx_kernel<<<dim3(Bn * Hh, NSPLIT), thr>>>(k, v, ctxp);
    att_kernel<<<dim3(Ln / 256, Bn * Hh), thr>>>(ctxp, q, att);

    // Reprojection + residual
    conv_x<<<dim3(8, 16, 8), thr>>>(att, hf + OFF_ATTC, 512);
    gemm_wm<<<dim3(4, 32, 8), 256, GEMM_SMEM>>>(hf + OFF_WR, br, hf + OFF_ATTC, z, z1, 512, 512, 0);

    // LN1
    ln_kernel<<<Bn * (Ln / 32), thr>>>(z, z, g1, be1);

    // FFN
    conv_x<<<dim3(8, 16, 8), thr>>>(z, hf + OFF_ZC, 512);
    gemm_wm<<<dim3(8, 32, 8), 256, GEMM_SMEM>>>(hf + OFF_W1, b1, hf + OFF_ZC, h, nullptr, 1024, 512, 1);
    conv_x<<<dim3(16, 16, 8), thr>>>(h, hf + OFF_HC, 1024);
    gemm_wm<<<dim3(4, 32, 8), 256, GEMM_SMEM>>>(hf + OFF_W2, b2, hf + OFF_HC, y, nullptr, 512, 1024, 0);

    // LN2 -> output
    ln_kernel<<<Bn * (Ln / 32), thr>>>(y, (float*)d_out, g2, be2);
}

// round 6
// speedup vs baseline: 4.3251x; 1.1597x over previous
#include <cuda_runtime.h>
#include <cuda_fp16.h>
#include <cstdint>

// Problem constants
#define Bn  8
#define Cc  512
#define Ln  4096
#define Hh  8
#define Dh  64
#define NSPLIT 4

// ---------------------------------------------------------------------------
// Scratch
// ---------------------------------------------------------------------------
__device__ float g_scratch[135266304];
// fp16 converted/pre-tiled operands (single plane)
__device__ __half g_hf[102760448];

// half-element offsets into g_hf
#define OFF_Z1C  0ull
#define OFF_Z2C  16777216ull
#define OFF_ATTC 33554432ull
#define OFF_ZC   50331648ull
#define OFF_HC   67108864ull
#define OFF_WQ   100663296ull
#define OFF_WK   100925440ull
#define OFF_WV   101187584ull
#define OFF_WR   101449728ull
#define OFF_W1   101711872ull
#define OFF_W2   102236160ull

// ---------------------------------------------------------------------------
// Helpers
// ---------------------------------------------------------------------------
__device__ __forceinline__ uint32_t smem_u32(const void* p) {
    uint32_t a;
    asm("{ .reg .u64 t; cvta.to.shared.u64 t, %1; cvt.u32.u64 %0, t; }"
        : "=r"(a) : "l"(p));
    return a;
}
__device__ __host__ __forceinline__ uint32_t swz128(uint32_t off) {
    return off ^ ((off >> 3) & 0x70);
}
__device__ __forceinline__ void cpasync16(uint32_t d, const void* s) {
    asm volatile("cp.async.cg.shared.global [%0], [%1], 16;" :: "r"(d), "l"(s));
}
#define CP_COMMIT() asm volatile("cp.async.commit_group;" ::: "memory")
#define CP_WAIT(N)  asm volatile("cp.async.wait_group " #N ";" ::: "memory")

#define LDSM4(R, ADDR) \
    asm volatile("ldmatrix.sync.aligned.m8n8.x4.shared.b16 {%0,%1,%2,%3}, [%4];" \
        : "=r"((R)[0]), "=r"((R)[1]), "=r"((R)[2]), "=r"((R)[3]) : "r"(ADDR))

#define MMA16816(C, A, Bv) \
    asm volatile("mma.sync.aligned.m16n8k16.row.col.f32.f16.f16.f32 " \
        "{%0,%1,%2,%3}, {%4,%5,%6,%7}, {%8,%9}, {%0,%1,%2,%3};" \
        : "+f"((C)[0]), "+f"((C)[1]), "+f"((C)[2]), "+f"((C)[3]) \
        : "r"((A)[0]), "r"((A)[1]), "r"((A)[2]), "r"((A)[3]), \
          "r"((Bv)[0]), "r"((Bv)[1]))

__device__ __forceinline__ uint32_t pack2h(float a, float b) {
    __half2 h = __floats2half2_rn(a, b);
    return *(uint32_t*)&h;
}

// ---------------------------------------------------------------------------
// Convert W [M,K] fp32 -> pre-tiled swizzled fp16 blocks (16KB per (mt,kc))
// ---------------------------------------------------------------------------
__global__ __launch_bounds__(256) void conv_w(
    const float* __restrict__ src, __half* __restrict__ dstb, int K)
{
    int kc = blockIdx.x, mt = blockIdx.y;
    int NC = K >> 6;
    char* db = (char*)(dstb + ((size_t)(mt * NC + kc)) * 8192);
    const float* sb = src + ((size_t)mt * 128) * K + kc * 64;
    for (int it = 0; it < 4; it++) {
        int u = threadIdx.x + 256 * it;
        int r = u >> 3, g = u & 7;
        float x0[8];
        #pragma unroll
        for (int q = 0; q < 2; q++) {
            float4 v = *(const float4*)(sb + (size_t)r * K + g * 8 + q * 4);
            x0[q*4+0]=v.x; x0[q*4+1]=v.y; x0[q*4+2]=v.z; x0[q*4+3]=v.w;
        }
        uint4 w;
        w.x = pack2h(x0[0], x0[1]);
        w.y = pack2h(x0[2], x0[3]);
        w.z = pack2h(x0[4], x0[5]);
        w.w = pack2h(x0[6], x0[7]);
        uint32_t sw = swz128((uint32_t)r * 128 + g * 16);
        *(uint4*)(db + sw) = w;
    }
}

// ---------------------------------------------------------------------------
// Convert+transpose X [B,K,L] fp32 -> tiled blocks (32KB per (b,lt256,kc))
// ---------------------------------------------------------------------------
__global__ __launch_bounds__(256) void conv_x(
    const float* __restrict__ src, __half* __restrict__ dstb, int K)
{
    int kc = blockIdx.x, lt = blockIdx.y, b = blockIdx.z;
    int NC = K >> 6;
    __shared__ float sm[32][264];
    const float* sb = src + ((size_t)b * K + kc * 64) * Ln + (size_t)lt * 256;
    char* db = (char*)(dstb + (((size_t)b * 16 + lt) * NC + kc) * 16384);
    int t = threadIdx.x;
    for (int p = 0; p < 2; p++) {
        __syncthreads();
        #pragma unroll
        for (int i = 0; i < 8; i++) {
            int u = t + 256 * i;
            int kr = u >> 6;
            int lc = u & 63;
            float4 v = *(const float4*)(sb + ((size_t)(p * 32 + kr)) * Ln + lc * 4);
            sm[kr][lc*4+0]=v.x; sm[kr][lc*4+1]=v.y; sm[kr][lc*4+2]=v.z; sm[kr][lc*4+3]=v.w;
        }
        __syncthreads();
        #pragma unroll
        for (int g = 0; g < 4; g++) {
            float x0[8];
            #pragma unroll
            for (int j = 0; j < 8; j++) x0[j] = sm[g*8+j][t];
            uint4 w;
            w.x = pack2h(x0[0], x0[1]);
            w.y = pack2h(x0[2], x0[3]);
            w.z = pack2h(x0[4], x0[5]);
            w.w = pack2h(x0[6], x0[7]);
            uint32_t sw = swz128((uint32_t)t * 128 + (p * 32 + g * 8) * 2);
            *(uint4*)(db + sw) = w;
        }
    }
}

// ---------------------------------------------------------------------------
// Warp-MMA fp16 GEMM. outmode 0: fp32 Out (+Res)(+ELU). outmode 1: fp16 tiled
// Outh (+ELU), GEMM-input block format, via smem-staged transpose.
// ---------------------------------------------------------------------------
__global__ __launch_bounds__(256, 2) void gemm_wm(
    const __half* __restrict__ Wc, const float* __restrict__ bias,
    const __half* __restrict__ Xc, float* __restrict__ Out,
    __half* __restrict__ Outh,
    const float* __restrict__ Res, int M, int K, int act, int outmode)
{
    extern __shared__ __align__(1024) char smem[];
    const int NC = K >> 6;
    int tid = threadIdx.x, wid = tid >> 5, lane = tid & 31;
    int mt = blockIdx.x, lt = blockIdx.y, b = blockIdx.z;
    int wm = wid >> 2, wn = wid & 3;
    int sub = lane >> 3, r = lane & 7;

    const char* Abase = (const char*)Wc + ((size_t)mt * NC) * 16384;
    int lt256 = lt >> 1, half = lt & 1;
    const char* Bbase = (const char*)Xc + (((size_t)b * 16 + lt256) * NC) * 32768
                        + (size_t)half * 16384;

    uint32_t sbase = smem_u32(smem);

    uint32_t aRow[4], aMask[4];
    int kaddA = (sub >> 1) * 16;
    #pragma unroll
    for (int i = 0; i < 4; i++) {
        uint32_t row = wm * 64 + i * 16 + (sub & 1) * 8 + r;
        aRow[i] = row * 128;
        aMask[i] = (aRow[i] >> 3) & 0x70;
    }
    uint32_t bRow[2], bMask[2];
    int kaddB = (sub & 1) * 16;
    #pragma unroll
    for (int j = 0; j < 2; j++) {
        uint32_t row = wn * 32 + j * 16 + (sub >> 1) * 8 + r;
        bRow[j] = row * 128;
        bMask[j] = (bRow[j] >> 3) & 0x70;
    }

    float acc[4][4][4];
    #pragma unroll
    for (int i = 0; i < 4; i++)
        #pragma unroll
        for (int j = 0; j < 4; j++)
            #pragma unroll
            for (int q = 0; q < 4; q++) acc[i][j][q] = 0.f;

    auto load_stage = [&](int kc, int s) {
        uint32_t S = sbase + (uint32_t)s * 32768;
        const char* ah = Abase + (size_t)kc * 16384;
        const char* bh = Bbase + (size_t)kc * 32768;
        #pragma unroll
        for (int q = 0; q < 4; q++) {
            uint32_t off = (uint32_t)tid * 64 + q * 16;
            cpasync16(S + off,         ah + off);
            cpasync16(S + 16384 + off, bh + off);
        }
    };

    load_stage(0, 0);
    CP_COMMIT();

    for (int c = 0; c < NC; c++) {
        if (c + 1 < NC) {
            load_stage(c + 1, (c + 1) & 1);
            CP_COMMIT();
            CP_WAIT(1);
        } else {
            CP_WAIT(0);
        }
        __syncthreads();

        uint32_t S = sbase + (uint32_t)(c & 1) * 32768;
        #pragma unroll
        for (int kk = 0; kk < 4; kk++) {
            int kb = kk * 32;
            uint32_t aa[16], bb[8];
            #pragma unroll
            for (int i = 0; i < 4; i++)
                LDSM4(&aa[i * 4], S + aRow[i] + (uint32_t)((kaddA + kb) ^ aMask[i]));
            #pragma unroll
            for (int j = 0; j < 2; j++)
                LDSM4(&bb[j * 4], S + 16384 + bRow[j] + (uint32_t)((kaddB + kb) ^ bMask[j]));
            #pragma unroll
            for (int mi = 0; mi < 4; mi++)
                #pragma unroll
                for (int nj = 0; nj < 4; nj++)
                    MMA16816(acc[mi][nj], &aa[mi * 4], &bb[nj * 2]);
        }
        __syncthreads();
    }

    int g = lane >> 2, tg = lane & 3;

    if (outmode == 0) {
        #pragma unroll
        for (int mi = 0; mi < 4; mi++) {
            #pragma unroll
            for (int h2 = 0; h2 < 2; h2++) {
                int m = mt * 128 + wm * 64 + mi * 16 + h2 * 8 + g;
                float bi = bias[m];
                size_t rowoff = ((size_t)b * M + m) * Ln + (size_t)lt * 128 + wn * 32;
                #pragma unroll
                for (int nj = 0; nj < 4; nj++) {
                    int col = nj * 8 + 2 * tg;
                    float v0 = acc[mi][nj][h2 * 2 + 0] + bi;
                    float v1 = acc[mi][nj][h2 * 2 + 1] + bi;
                    if (Res) {
                        float2 r2 = *(const float2*)(Res + rowoff + col);
                        v0 += r2.x; v1 += r2.y;
                    }
                    if (act) {
                        v0 = v0 > 0.f ? v0 : expm1f(v0);
                        v1 = v1 > 0.f ? v1 : expm1f(v1);
                    }
                    *(float2*)(Out + rowoff + col) = make_float2(v0, v1);
                }
            }
        }
    } else {
        // Stage fp16 tile transposed: rows l (0..127), pitch 136 halves
        __half* smh = (__half*)smem;
        #pragma unroll
        for (int mi = 0; mi < 4; mi++) {
            #pragma unroll
            for (int h2 = 0; h2 < 2; h2++) {
                int ml = wm * 64 + mi * 16 + h2 * 8 + g;
                float bi = bias[mt * 128 + ml];
                #pragma unroll
                for (int nj = 0; nj < 4; nj++) {
                    int ll = wn * 32 + nj * 8 + 2 * tg;
                    float v0 = acc[mi][nj][h2 * 2 + 0] + bi;
                    float v1 = acc[mi][nj][h2 * 2 + 1] + bi;
                    if (act) {
                        v0 = v0 > 0.f ? v0 : expm1f(v0);
                        v1 = v1 > 0.f ? v1 : expm1f(v1);
                    }
                    smh[(uint32_t)ll * 136 + ml]       = __float2half(v0);
                    smh[(uint32_t)(ll + 1) * 136 + ml] = __float2half(v1);
                }
            }
        }
        __syncthreads();
        int rowbase = (lt & 1) * 128;
        int NCo = M >> 6;
        #pragma unroll
        for (int kc = 0; kc < 2; kc++) {
            char* db = (char*)(Outh + (((size_t)b * 16 + lt256) * NCo + (mt * 2 + kc)) * 16384);
            #pragma unroll
            for (int it = 0; it < 4; it++) {
                int u = tid + 256 * it;          // 0..1023
                int row = u >> 3, j = u & 7;
                uint4 w = *(uint4*)&smh[(uint32_t)row * 136 + kc * 64 + j * 8];
                *(uint4*)(db + swz128((uint32_t)(rowbase + row) * 128 + j * 16)) = w;
            }
        }
    }
}

// ---------------------------------------------------------------------------
// Softmax over length (contiguous Ln rows)
// ---------------------------------------------------------------------------
__global__ __launch_bounds__(256) void softmax_len(float* __restrict__ data)
{
    __shared__ float red[256];
    float* p = data + (size_t)blockIdx.x * Ln;
    int t = threadIdx.x;
    float v[16];
    float m = -1e30f;
    #pragma unroll
    for (int i = 0; i < 16; i++) { v[i] = p[t + 256 * i]; m = fmaxf(m, v[i]); }
    red[t] = m; __syncthreads();
    for (int off = 128; off > 0; off >>= 1) {
        if (t < off) red[t] = fmaxf(red[t], red[t + off]);
        __syncthreads();
    }
    m = red[0];
    __syncthreads();
    float s = 0.f;
    #pragma unroll
    for (int i = 0; i < 16; i++) { v[i] = __expf(v[i] - m); s += v[i]; }
    red[t] = s; __syncthreads();
    for (int off = 128; off > 0; off >>= 1) {
        if (t < off) red[t] += red[t + off];
        __syncthreads();
    }
    float inv = 1.f / red[0];
    #pragma unroll
    for (int i = 0; i < 16; i++) p[t + 256 * i] = v[i] * inv;
}

// ---------------------------------------------------------------------------
// ctx partials
// ---------------------------------------------------------------------------
__global__ __launch_bounds__(256) void ctx_kernel(
    const float* __restrict__ kk, const float* __restrict__ vv,
    float* __restrict__ ctxp)
{
    int bh = blockIdx.x;
    int sp = blockIdx.y;
    const float* kb = kk + (size_t)bh * Dh * Ln;
    const float* vb = vv + (size_t)bh * Dh * Ln;

    __shared__ float ks[64][33];
    __shared__ float vs[64][33];

    int tid = threadIdx.x;
    int lt = tid & 31, dr = tid >> 5;
    int tx = tid & 15, ty = tid >> 4;

    float acc[4][4];
    #pragma unroll
    for (int i = 0; i < 4; i++)
        #pragma unroll
        for (int j = 0; j < 4; j++) acc[i][j] = 0.f;

    int lbeg = sp * (Ln / NSPLIT);
    int lend = lbeg + (Ln / NSPLIT);
    for (int l0 = lbeg; l0 < lend; l0 += 32) {
        __syncthreads();
        #pragma unroll
        for (int r = 0; r < 8; r++) {
            int dk = dr + 8 * r;
            ks[dk][lt] = kb[(size_t)dk * Ln + l0 + lt];
            vs[dk][lt] = vb[(size_t)dk * Ln + l0 + lt];
        }
        __syncthreads();
        #pragma unroll
        for (int l2 = 0; l2 < 32; l2++) {
            float av[4], bw[4];
            #pragma unroll
            for (int i = 0; i < 4; i++) av[i] = ks[ty * 4 + i][l2];
            #pragma unroll
            for (int j = 0; j < 4; j++) bw[j] = vs[tx * 4 + j][l2];
            #pragma unroll
            for (int i = 0; i < 4; i++)
                #pragma unroll
                for (int j = 0; j < 4; j++)
                    acc[i][j] += av[i] * bw[j];
        }
    }
    #pragma unroll
    for (int i = 0; i < 4; i++)
        #pragma unroll
        for (int j = 0; j < 4; j++) {
            int dk = ty * 4 + i, dv = tx * 4 + j;
            ctxp[(((size_t)sp * 64 + bh) * 64 + dk) * 64 + dv] = acc[i][j];
        }
}

// ---------------------------------------------------------------------------
// att fused: head-softmax(q) inline + ctx^T apply + fp16 tiled output
// grid (Ln/256, Bn*Hh), 256 threads. One CTA = one 256x64 tiled block.
// ---------------------------------------------------------------------------
__global__ __launch_bounds__(256) void att_fused(
    const float* __restrict__ ctxp, const float* __restrict__ q,
    __half* __restrict__ attc)
{
    int bh = blockIdx.y;
    int b = bh >> 3, h = bh & 7;
    __shared__ float cs[64][64];
    int tid = threadIdx.x;

    float4* cs4 = (float4*)cs;
    #pragma unroll
    for (int r = 0; r < 4; r++) {
        int idx = tid + 256 * r;
        float4 sum = make_float4(0.f, 0.f, 0.f, 0.f);
        #pragma unroll
        for (int s = 0; s < NSPLIT; s++) {
            const float4* p = (const float4*)(ctxp + ((size_t)s * 64 + bh) * 4096);
            float4 t = p[idx];
            sum.x += t.x; sum.y += t.y; sum.z += t.z; sum.w += t.w;
        }
        cs4[idx] = sum;
    }
    __syncthreads();

    int l = blockIdx.x * 256 + tid;
    const float* qb = q + (size_t)bh * Dh * Ln + l;

    // head-channel softmax in registers
    float qv[64];
    float mx = -1e30f;
    #pragma unroll
    for (int d = 0; d < 64; d++) { qv[d] = qb[(size_t)d * Ln]; mx = fmaxf(mx, qv[d]); }
    float s = 0.f;
    #pragma unroll
    for (int d = 0; d < 64; d++) { qv[d] = __expf(qv[d] - mx); s += qv[d]; }
    float inv = 1.f / s;

    float acc[64];
    #pragma unroll
    for (int d = 0; d < 64; d++) acc[d] = 0.f;

    #pragma unroll 4
    for (int dk = 0; dk < 64; dk++) {
        float qq = qv[dk] * inv;
        #pragma unroll
        for (int j = 0; j < 16; j++) {
            float4 c4 = *(const float4*)&cs[dk][j * 4];
            acc[4 * j + 0] += c4.x * qq;
            acc[4 * j + 1] += c4.y * qq;
            acc[4 * j + 2] += c4.z * qq;
            acc[4 * j + 3] += c4.w * qq;
        }
    }

    // write fp16 tiled block (b, blockIdx.x, kc=h); row = tid, cols = 64 dv
    char* db = (char*)(attc + (((size_t)b * 16 + blockIdx.x) * 8 + h) * 16384);
    #pragma unroll
    for (int j = 0; j < 8; j++) {
        uint4 w;
        w.x = pack2h(acc[8*j+0], acc[8*j+1]);
        w.y = pack2h(acc[8*j+2], acc[8*j+3]);
        w.z = pack2h(acc[8*j+4], acc[8*j+5]);
        w.w = pack2h(acc[8*j+6], acc[8*j+7]);
        *(uint4*)(db + swz128((uint32_t)tid * 128 + j * 16)) = w;
    }
}

// ---------------------------------------------------------------------------
// Channel LayerNorm over C=512 -> fp32 out (channel-first)
// ---------------------------------------------------------------------------
__global__ __launch_bounds__(256) void ln_kernel(
    const float* __restrict__ in, float* __restrict__ out,
    const float* __restrict__ g, const float* __restrict__ be)
{
    __shared__ float ss[8][32], sq[8][32], smean[32], srstd[32];
    int blk = blockIdx.x;
    int b = blk >> 7;
    int li = threadIdx.x & 31;
    int l = ((blk & 127) << 5) + li;
    int r = threadIdx.x >> 5;
    const float* base = in + (size_t)b * Cc * Ln + l;

    float s = 0.f, s2 = 0.f;
    #pragma unroll
    for (int k2 = 0; k2 < 64; k2++) {
        int c = r * 64 + k2;
        float x = base[(size_t)c * Ln];
        s += x; s2 += x * x;
    }
    ss[r][li] = s; sq[r][li] = s2;
    __syncthreads();
    if (r == 0) {
        float ts = ss[0][li], t2 = sq[0][li];
        #pragma unroll
        for (int rr = 1; rr < 8; rr++) { ts += ss[rr][li]; t2 += sq[rr][li]; }
        float mean = ts * (1.f / 512.f);
        float var = t2 * (1.f / 512.f) - mean * mean;
        smean[li] = mean;
        srstd[li] = rsqrtf(var + 1e-5f);
    }
    __syncthreads();
    float mean = smean[li], rstd = srstd[li];
    float* ob = out + (size_t)b * Cc * Ln + l;
    #pragma unroll
    for (int k2 = 0; k2 < 64; k2++) {
        int c = r * 64 + k2;
        float x = base[(size_t)c * Ln];
        ob[(size_t)c * Ln] = (x - mean) * rstd * g[c] + be[c];
    }
}

// ---------------------------------------------------------------------------
// Channel LayerNorm -> fp16 tiled out (GEMM-input block format)
// Thread (r, li): 64 channels of group r at l -> one tile row.
// ---------------------------------------------------------------------------
__global__ __launch_bounds__(256) void ln_h(
    const float* __restrict__ in, __half* __restrict__ outc,
    const float* __restrict__ g, const float* __restrict__ be)
{
    __shared__ float ss[8][32], sq[8][32], smean[32], srstd[32];
    int blk = blockIdx.x;
    int b = blk >> 7;
    int li = threadIdx.x & 31;
    int l = ((blk & 127) << 5) + li;
    int r = threadIdx.x >> 5;
    const float* base = in + (size_t)b * Cc * Ln + l;

    float s = 0.f, s2 = 0.f;
    float x0[64];
    #pragma unroll
    for (int k2 = 0; k2 < 64; k2++) {
        int c = r * 64 + k2;
        float x = base[(size_t)c * Ln];
        x0[k2] = x;
        s += x; s2 += x * x;
    }
    ss[r][li] = s; sq[r][li] = s2;
    __syncthreads();
    if (r == 0) {
        float ts = ss[0][li], t2 = sq[0][li];
        #pragma unroll
        for (int rr = 1; rr < 8; rr++) { ts += ss[rr][li]; t2 += sq[rr][li]; }
        float mean = ts * (1.f / 512.f);
        float var = t2 * (1.f / 512.f) - mean * mean;
        smean[li] = mean;
        srstd[li] = rsqrtf(var + 1e-5f);
    }
    __syncthreads();
    float mean = smean[li], rstd = srstd[li];

    char* db = (char*)(outc + (((size_t)b * 16 + (l >> 8)) * 8 + r) * 16384);
    uint32_t row = (uint32_t)(l & 255);
    #pragma unroll
    for (int j = 0; j < 8; j++) {
        float v[8];
        #pragma unroll
        for (int q2 = 0; q2 < 8; q2++) {
            int c = r * 64 + j * 8 + q2;
            v[q2] = (x0[j * 8 + q2] - mean) * rstd * g[c] + be[c];
        }
        uint4 w;
        w.x = pack2h(v[0], v[1]);
        w.y = pack2h(v[2], v[3]);
        w.z = pack2h(v[4], v[5]);
        w.w = pack2h(v[6], v[7]);
        *(uint4*)(db + swz128(row * 128 + j * 16)) = w;
    }
}

// ---------------------------------------------------------------------------
extern "C" void kernel_launch(void* const* d_in, const int* in_sizes, int n_in,
                              void* d_out, int out_size)
{
    const float* z1  = (const float*)d_in[0];
    const float* z2  = (const float*)d_in[1];
    const float* Wq  = (const float*)d_in[2];
    const float* bq  = (const float*)d_in[3];
    const float* Wk  = (const float*)d_in[4];
    const float* bkb = (const float*)d_in[5];
    const float* Wv  = (const float*)d_in[6];
    const float* bv  = (const float*)d_in[7];
    const float* Wr  = (const float*)d_in[8];
    const float* br  = (const float*)d_in[9];
    const float* g1  = (const float*)d_in[10];
    const float* be1 = (const float*)d_in[11];
    const float* W1  = (const float*)d_in[12];
    const float* b1  = (const float*)d_in[13];
    const float* W2  = (const float*)d_in[14];
    const float* b2  = (const float*)d_in[15];
    const float* g2  = (const float*)d_in[16];
    const float* be2 = (const float*)d_in[17];

    float* fs = nullptr;
    cudaGetSymbolAddress((void**)&fs, g_scratch);
    __half* hf = nullptr;
    cudaGetSymbolAddress((void**)&hf, g_hf);

    const size_t SZ = (size_t)Bn * Cc * Ln;   // 16777216
    float* q    = fs;
    float* k    = fs + SZ;
    float* v    = fs + 2 * SZ;
    float* z    = fs + 4 * SZ;
    float* y    = fs + 5 * SZ;
    float* ctxp = fs + 8 * SZ;

    const int GEMM_SMEM = 65536;
    cudaFuncSetAttribute(gemm_wm, cudaFuncAttributeMaxDynamicSharedMemorySize, GEMM_SMEM);

    dim3 thr(256);
    // Weight conversions
    conv_w<<<dim3(8, 4), thr>>>(Wq, hf + OFF_WQ, 512);
    conv_w<<<dim3(8, 4), thr>>>(Wk, hf + OFF_WK, 512);
    conv_w<<<dim3(8, 4), thr>>>(Wv, hf + OFF_WV, 512);
    conv_w<<<dim3(8, 4), thr>>>(Wr, hf + OFF_WR, 512);
    conv_w<<<dim3(8, 8), thr>>>(W1, hf + OFF_W1, 512);
    conv_w<<<dim3(16, 4), thr>>>(W2, hf + OFF_W2, 1024);

    // Input conversions
    conv_x<<<dim3(8, 16, 8), thr>>>(z1, hf + OFF_Z1C, 512);
    conv_x<<<dim3(8, 16, 8), thr>>>(z2, hf + OFF_Z2C, 512);

    // Projections (warp-MMA fp16, fp32 out)
    gemm_wm<<<dim3(4, 32, 8), 256, GEMM_SMEM>>>(hf + OFF_WQ, bq,  hf + OFF_Z1C, q, nullptr, nullptr, 512, 512, 0, 0);
    gemm_wm<<<dim3(4, 32, 8), 256, GEMM_SMEM>>>(hf + OFF_WK, bkb, hf + OFF_Z2C, k, nullptr, nullptr, 512, 512, 0, 0);
    gemm_wm<<<dim3(4, 32, 8), 256, GEMM_SMEM>>>(hf + OFF_WV, bv,  hf + OFF_Z2C, v, nullptr, nullptr, 512, 512, 0, 0);

    // key softmax over length
    softmax_len<<<Bn * Cc, thr>>>(k);

    // Attention core: ctx partials, then fused (softmax_q + apply + fp16 tile)
    ctx_kernel<<<dim3(Bn * Hh, NSPLIT), thr>>>(k, v, ctxp);
    att_fused<<<dim3(Ln / 256, Bn * Hh), thr>>>(ctxp, q, hf + OFF_ATTC);

    // Reprojection + residual (fp32 out)
    gemm_wm<<<dim3(4, 32, 8), 256, GEMM_SMEM>>>(hf + OFF_WR, br, hf + OFF_ATTC, z, nullptr, z1, 512, 512, 0, 0);

    // LN1 -> fp16 tiled
    ln_h<<<Bn * (Ln / 32), thr>>>(z, hf + OFF_ZC, g1, be1);

    // FFN1 -> fp16 tiled h (ELU fused), FFN2 -> fp32 y
    gemm_wm<<<dim3(8, 32, 8), 256, GEMM_SMEM>>>(hf + OFF_W1, b1, hf + OFF_ZC, nullptr, hf + OFF_HC, nullptr, 1024, 512, 1, 1);
    gemm_wm<<<dim3(4, 32, 8), 256, GEMM_SMEM>>>(hf + OFF_W2, b2, hf + OFF_HC, y, nullptr, nullptr, 512, 1024, 0, 0);

    // LN2 -> output
    ln_kernel<<<Bn * (Ln / 32), thr>>>(y, (float*)d_out, g2, be2);
}